// round 13
// baseline (speedup 1.0000x reference)
#include <cuda_runtime.h>
#include <cuda_fp16.h>

#define H_DIM 512
#define W_DIM 512
#define RPB   8       // rows per strip; block = 2 strips = 16 rows
#define NTHREADS 128
#define MAX_BLOCKS 8192

__device__ float    g_part[MAX_BLOCKS];
__device__ unsigned g_ticket;   // zero-init; restored to 0 by last block each run

// Raw per-row data: 8 px (two float4) + clamped halo scalars.
struct Raw8 { float4 v0, v1; float m, p; };

__device__ __forceinline__ Raw8 ldrow8(const float* __restrict__ row,
                                       int x0, int xm, int xp) {
    Raw8 r;
    r.v0 = *reinterpret_cast<const float4*>(row + x0);
    r.v1 = *reinterpret_cast<const float4*>(row + x0 + 4);
    r.m  = __ldg(row + xm);
    r.p  = __ldg(row + xp);
    return r;
}

// Per-row Sobel pieces for 8 px as 4 half2 pixel-pairs:
//   d = val(x-1) - val(x+1) ; s = val(x-1) + 2 val(x) + val(x+1)
// Shifted pairs A0=(m,h0) B0=(h1,h2) B1=(h3,h4) B2=(h5,h6) B3=(h7,p)
// Natural pairs N0=(h0,h1) N1=(h2,h3) N2=(h4,h5) N3=(h6,h7)
//   d[j] = (A0,B0,B1,B2)[j] - (B0,B1,B2,B3)[j]
//   s[j] = 2*N[j] + (A0,B0,B1,B2)[j] + (B0,B1,B2,B3)[j]
struct HS8 { __half2 d[4], s[4]; };

__device__ __forceinline__ HS8 mk_hs8(const Raw8& a, __half2 two2) {
    __half2 A0 = __floats2half2_rn(a.m,    a.v0.x);
    __half2 B0 = __floats2half2_rn(a.v0.y, a.v0.z);
    __half2 B1 = __floats2half2_rn(a.v0.w, a.v1.x);
    __half2 B2 = __floats2half2_rn(a.v1.y, a.v1.z);
    __half2 B3 = __floats2half2_rn(a.v1.w, a.p);
    __half2 N0 = __floats2half2_rn(a.v0.x, a.v0.y);
    __half2 N1 = __floats2half2_rn(a.v0.z, a.v0.w);
    __half2 N2 = __floats2half2_rn(a.v1.x, a.v1.y);
    __half2 N3 = __floats2half2_rn(a.v1.z, a.v1.w);
    HS8 r;
    r.d[0] = __hsub2(A0, B0);
    r.d[1] = __hsub2(B0, B1);
    r.d[2] = __hsub2(B1, B2);
    r.d[3] = __hsub2(B2, B3);
    r.s[0] = __hadd2(__hfma2(two2, N0, A0), B0);
    r.s[1] = __hadd2(__hfma2(two2, N1, B0), B1);
    r.s[2] = __hadd2(__hfma2(two2, N2, B1), B2);
    r.s[3] = __hadd2(__hfma2(two2, N3, B2), B3);
    return r;
}

// Packed normal for a pixel pair, fully in half2:
//   q = gx^2+gy^2 ; length^2 = 0.0625 + 3.9375 q ; w = h2rsqrt(.) = 1/length
//   nx = gx*w, ny = gy*w, 4*nz = (1 - q/2)*w
__device__ __forceinline__ void nrm2(__half2 dP, __half2 dC, __half2 dN,
                                     __half2 sP, __half2 sN,
                                     __half2 two2, __half2 one2,
                                     __half2 c3, __half2 c0, __half2 cb,
                                     __half2& nx, __half2& ny, __half2& z4) {
    __half2 gx = __hadd2(__hfma2(two2, dC, dP), dN);
    __half2 gy = __hsub2(sP, sN);
    __half2 q  = __hfma2(gx, gx, __hmul2(gy, gy));
    __half2 w2 = h2rsqrt(__hfma2(c3, q, c0));
    __half2 su = __hfma2(cb, q, one2);             // 1 - q/2
    nx = __hmul2(gx, w2);
    ny = __hmul2(gy, w2);
    z4 = __hmul2(su, w2);      // 4*nz ; 0.25 folded into the final reduction
}

__global__ void __launch_bounds__(NTHREADS, 6)
heightmap_loss_kernel(const float* __restrict__ gen, const float* __restrict__ tgt,
                      float* __restrict__ out, double inv_n) {
    const int b     = blockIdx.y;
    const int strip = threadIdx.x >> 6;            // 0 or 1
    const int tx    = threadIdx.x & 63;
    const int y0    = blockIdx.x * (2 * RPB) + strip * RPB;
    const int lane  = threadIdx.x & 31;
    const int x0    = tx * 8;
    const int xm    = max(x0 - 1, 0);
    const int xp    = min(x0 + 8, W_DIM - 1);
    const int nblocks = gridDim.x * gridDim.y;
    const int bid     = blockIdx.y * gridDim.x + blockIdx.x;

    const __half2 two2 = __float2half2_rn(2.f);
    const __half2 one2 = __float2half2_rn(1.f);
    const __half2 c3   = __float2half2_rn(3.9375f);
    const __half2 c0   = __float2half2_rn(0.0625f);
    const __half2 cb   = __float2half2_rn(-0.5f);

    const float* __restrict__ gimg = gen + (size_t)b * (H_DIM * W_DIM);
    const float* __restrict__ timg = tgt + (size_t)b * (H_DIM * W_DIM);

    // rolling 3-row window (prev, cur, next) per image, in half2
    HS8 gP, gC, gN, tP, tC, tN;
    {
        int ym = max(y0 - 1, 0);
        gP = mk_hs8(ldrow8(gimg + ym * W_DIM, x0, xm, xp), two2);
        tP = mk_hs8(ldrow8(timg + ym * W_DIM, x0, xm, xp), two2);
        gC = mk_hs8(ldrow8(gimg + y0 * W_DIM, x0, xm, xp), two2);
        tC = mk_hs8(ldrow8(timg + y0 * W_DIM, x0, xm, xp), two2);
    }

    // independent packed accumulator pairs (A: quads 0,2 ; B: quads 1,3)
    __half2 axyA = __float2half2_rn(0.f), azA = axyA;
    __half2 axyB = axyA, azB = axyA;

    #pragma unroll
    for (int yy = 0; yy < RPB; yy++) {
        int yn = min(y0 + yy + 1, H_DIM - 1);
        Raw8 gr = ldrow8(gimg + yn * W_DIM, x0, xm, xp);
        Raw8 tr = ldrow8(timg + yn * W_DIM, x0, xm, xp);
        gN = mk_hs8(gr, two2);
        tN = mk_hs8(tr, two2);

        #pragma unroll
        for (int j = 0; j < 4; j++) {
            __half2 gnx, gny, gz4, tnx, tny, tz4;
            nrm2(gP.d[j], gC.d[j], gN.d[j], gP.s[j], gN.s[j],
                 two2, one2, c3, c0, cb, gnx, gny, gz4);
            nrm2(tP.d[j], tC.d[j], tN.d[j], tP.s[j], tN.s[j],
                 two2, one2, c3, c0, cb, tnx, tny, tz4);
            __half2 dxy = __hadd2(__habs2(__hsub2(gnx, tnx)),
                                  __habs2(__hsub2(gny, tny)));
            __half2 dz  = __habs2(__hsub2(gz4, tz4));
            if (j & 1) { axyB = __hadd2(axyB, dxy); azB = __hadd2(azB, dz); }
            else       { axyA = __hadd2(axyA, dxy); azA = __hadd2(azA, dz); }
        }

        gP = gC; gC = gN;
        tP = tC; tC = tN;
    }

    // unpack to f32 and fold the 0.25 nz factor
    float axy = __low2float(axyA) + __high2float(axyA)
              + __low2float(axyB) + __high2float(axyB);
    float az  = __low2float(azA) + __high2float(azA)
              + __low2float(azB) + __high2float(azB);
    float acc = fmaf(0.25f, az, axy);

    // warp reduce
    #pragma unroll
    for (int o = 16; o > 0; o >>= 1)
        acc += __shfl_down_sync(0xffffffffu, acc, o);

    __shared__ float ws[NTHREADS / 32];
    __shared__ bool  isLast;
    if (lane == 0) ws[threadIdx.x >> 5] = acc;
    __syncthreads();
    if (threadIdx.x == 0) {
        g_part[bid] = ws[0] + ws[1] + ws[2] + ws[3];
        __threadfence();
        unsigned prev = atomicAdd(&g_ticket, 1u);
        isLast = (prev == (unsigned)(nblocks - 1));
    }
    __syncthreads();

    // Last block to finish performs the deterministic final reduction.
    if (isLast) {
        double s = 0.0;
        for (int i = threadIdx.x; i < nblocks; i += NTHREADS)
            s += (double)g_part[i];
        #pragma unroll
        for (int o = 16; o > 0; o >>= 1)
            s += __shfl_down_sync(0xffffffffu, s, o);
        __shared__ double ds[NTHREADS / 32];
        if (lane == 0) ds[threadIdx.x >> 5] = s;
        __syncthreads();
        if (threadIdx.x == 0) {
            double t = ds[0] + ds[1] + ds[2] + ds[3];
            out[0] = (float)(t * inv_n);
            g_ticket = 0u;   // restore invariant for graph replay
        }
    }
}

extern "C" void kernel_launch(void* const* d_in, const int* in_sizes, int n_in,
                              void* d_out, int out_size) {
    const float* gen = (const float*)d_in[0];
    const float* tgt = (const float*)d_in[1];
    float* out = (float*)d_out;

    const int total = in_sizes[0];              // B*1*H*W
    const int B = total / (H_DIM * W_DIM);

    dim3 grid(H_DIM / (2 * RPB), B);            // 32 x 32 = 1024 blocks
    heightmap_loss_kernel<<<grid, NTHREADS>>>(gen, tgt, out,
                                              1.0 / (3.0 * (double)total));
}

// round 14
// speedup vs baseline: 1.2117x; 1.2117x over previous
#include <cuda_runtime.h>
#include <cuda_fp16.h>

#define H_DIM 512
#define W_DIM 512
#define RPB   8       // output rows per block (2048 blocks)
#define NTHREADS 128  // 4 px/thread * 128 threads = 512 columns = full row
#define MAX_BLOCKS 8192

__device__ float    g_part[MAX_BLOCKS];
__device__ unsigned g_ticket;   // zero-init; restored to 0 by last block each run

// Raw per-row data: float4 + clamped halo scalars.
struct RawR { float4 v; float m, p; };

__device__ __forceinline__ RawR ldrow(const float* __restrict__ row,
                                      int x0, int xm, int xp) {
    RawR r;
    r.v = *reinterpret_cast<const float4*>(row + x0);
    r.m = __ldg(row + xm);
    r.p = __ldg(row + xp);
    return r;
}

// Per-row Sobel pieces in half2, pixel pairs (01) and (23):
//   d = val(x-1) - val(x+1) ; s = val(x-1) + 2 val(x) + val(x+1)
struct HS { __half2 d01, d23, s01, s23; };

__device__ __forceinline__ HS mk_hs(const RawR& a, __half2 two2) {
    // cvt.rn.f16x2.f32 packs two floats into one half2 in a single op
    __half2 mx = __floats2half2_rn(a.m,   a.v.x);
    __half2 xy = __floats2half2_rn(a.v.x, a.v.y);
    __half2 yz = __floats2half2_rn(a.v.y, a.v.z);
    __half2 zw = __floats2half2_rn(a.v.z, a.v.w);
    __half2 wp = __floats2half2_rn(a.v.w, a.p);
    HS r;
    r.d01 = __hsub2(mx, yz);                       // (m-y, x-z)
    r.d23 = __hsub2(yz, wp);                       // (y-w, z-p)
    r.s01 = __hadd2(__hfma2(two2, xy, mx), yz);    // (m+2x+y, x+2y+z)
    r.s23 = __hadd2(__hfma2(two2, zw, yz), wp);    // (y+2z+w, z+2w+p)
    return r;
}

// Packed normal for a pixel pair of one image, fully in half2:
//   q = gx^2+gy^2 ; length^2 = 0.0625 + 3.9375 q ; w = h2rsqrt(.) = 1/length
//   nx = gx*w, ny = gy*w, 4*nz = (1 - q/2)*w
__device__ __forceinline__ void nrm2(__half2 dP, __half2 dC, __half2 dN,
                                     __half2 sP, __half2 sN,
                                     __half2 two2, __half2 one2,
                                     __half2 c3, __half2 c0, __half2 cb,
                                     __half2& nx, __half2& ny, __half2& z4) {
    __half2 gx = __hadd2(__hfma2(two2, dC, dP), dN);
    __half2 gy = __hsub2(sP, sN);
    __half2 q  = __hfma2(gx, gx, __hmul2(gy, gy));
    __half2 w2 = h2rsqrt(__hfma2(c3, q, c0));
    __half2 su = __hfma2(cb, q, one2);             // 1 - q/2
    nx = __hmul2(gx, w2);
    ny = __hmul2(gy, w2);
    z4 = __hmul2(su, w2);      // 4*nz ; 0.25 folded into the final reduction
}

__global__ void __launch_bounds__(NTHREADS, 8)
heightmap_loss_kernel(const float* __restrict__ gen, const float* __restrict__ tgt,
                      float* __restrict__ out, double inv_n) {
    const int b    = blockIdx.y;
    const int y0   = blockIdx.x * RPB;
    const int lane = threadIdx.x & 31;
    const int x0   = threadIdx.x * 4;
    const int xm   = max(x0 - 1, 0);
    const int xp   = min(x0 + 4, W_DIM - 1);
    const int nblocks = gridDim.x * gridDim.y;
    const int bid     = blockIdx.y * gridDim.x + blockIdx.x;

    const __half2 two2 = __float2half2_rn(2.f);
    const __half2 one2 = __float2half2_rn(1.f);
    const __half2 c3   = __float2half2_rn(3.9375f);
    const __half2 c0   = __float2half2_rn(0.0625f);
    const __half2 cb   = __float2half2_rn(-0.5f);

    const float* __restrict__ gimg = gen + (size_t)b * (H_DIM * W_DIM);
    const float* __restrict__ timg = tgt + (size_t)b * (H_DIM * W_DIM);

    // rolling 3-row half2 window + 1-row raw prefetch buffer per image
    HS gP, gC, tP, tC;
    RawR gR, tR;     // raw data for the row that becomes N next iteration
    {
        int ym = max(y0 - 1, 0);
        gP = mk_hs(ldrow(gimg + ym * W_DIM, x0, xm, xp), two2);
        tP = mk_hs(ldrow(timg + ym * W_DIM, x0, xm, xp), two2);
        gC = mk_hs(ldrow(gimg + y0 * W_DIM, x0, xm, xp), two2);
        tC = mk_hs(ldrow(timg + y0 * W_DIM, x0, xm, xp), two2);
        gR = ldrow(gimg + (y0 + 1) * W_DIM, x0, xm, xp);   // y0+1 <= 505 < 512
        tR = ldrow(timg + (y0 + 1) * W_DIM, x0, xm, xp);
    }

    // independent packed accumulator pairs (A: px01, B: px23)
    __half2 axyA = __float2half2_rn(0.f), azA = axyA;
    __half2 axyB = axyA, azB = axyA;

    #pragma unroll
    for (int yy = 0; yy < RPB; yy++) {
        // Prefetch raw row yy+2 FIRST — consumers are a full iteration away.
        int yn2 = min(y0 + yy + 2, H_DIM - 1);
        RawR gR2 = ldrow(gimg + yn2 * W_DIM, x0, xm, xp);
        RawR tR2 = ldrow(timg + yn2 * W_DIM, x0, xm, xp);

        // N row from raw data loaded LAST iteration (already arrived).
        HS gN = mk_hs(gR, two2);
        HS tN = mk_hs(tR, two2);

        __half2 gnx, gny, gz4, tnx, tny, tz4;
        // pair 01
        nrm2(gP.d01, gC.d01, gN.d01, gP.s01, gN.s01,
             two2, one2, c3, c0, cb, gnx, gny, gz4);
        nrm2(tP.d01, tC.d01, tN.d01, tP.s01, tN.s01,
             two2, one2, c3, c0, cb, tnx, tny, tz4);
        axyA = __hadd2(axyA, __hadd2(__habs2(__hsub2(gnx, tnx)),
                                     __habs2(__hsub2(gny, tny))));
        azA  = __hadd2(azA, __habs2(__hsub2(gz4, tz4)));
        // pair 23
        nrm2(gP.d23, gC.d23, gN.d23, gP.s23, gN.s23,
             two2, one2, c3, c0, cb, gnx, gny, gz4);
        nrm2(tP.d23, tC.d23, tN.d23, tP.s23, tN.s23,
             two2, one2, c3, c0, cb, tnx, tny, tz4);
        axyB = __hadd2(axyB, __hadd2(__habs2(__hsub2(gnx, tnx)),
                                     __habs2(__hsub2(gny, tny))));
        azB  = __hadd2(azB, __habs2(__hsub2(gz4, tz4)));

        gP = gC; gC = gN; gR = gR2;
        tP = tC; tC = tN; tR = tR2;
    }

    // unpack to f32 and fold the 0.25 nz factor
    float axy = __low2float(axyA) + __high2float(axyA)
              + __low2float(axyB) + __high2float(axyB);
    float az  = __low2float(azA) + __high2float(azA)
              + __low2float(azB) + __high2float(azB);
    float acc = fmaf(0.25f, az, axy);

    // warp reduce
    #pragma unroll
    for (int o = 16; o > 0; o >>= 1)
        acc += __shfl_down_sync(0xffffffffu, acc, o);

    __shared__ float ws[NTHREADS / 32];
    __shared__ bool  isLast;
    if (lane == 0) ws[threadIdx.x >> 5] = acc;
    __syncthreads();
    if (threadIdx.x == 0) {
        g_part[bid] = ws[0] + ws[1] + ws[2] + ws[3];
        __threadfence();
        unsigned prev = atomicAdd(&g_ticket, 1u);
        isLast = (prev == (unsigned)(nblocks - 1));
    }
    __syncthreads();

    // Last block to finish performs the deterministic final reduction.
    if (isLast) {
        double s = 0.0;
        for (int i = threadIdx.x; i < nblocks; i += NTHREADS)
            s += (double)g_part[i];
        #pragma unroll
        for (int o = 16; o > 0; o >>= 1)
            s += __shfl_down_sync(0xffffffffu, s, o);
        __shared__ double ds[NTHREADS / 32];
        if (lane == 0) ds[threadIdx.x >> 5] = s;
        __syncthreads();
        if (threadIdx.x == 0) {
            double t = ds[0] + ds[1] + ds[2] + ds[3];
            out[0] = (float)(t * inv_n);
            g_ticket = 0u;   // restore invariant for graph replay
        }
    }
}

extern "C" void kernel_launch(void* const* d_in, const int* in_sizes, int n_in,
                              void* d_out, int out_size) {
    const float* gen = (const float*)d_in[0];
    const float* tgt = (const float*)d_in[1];
    float* out = (float*)d_out;

    const int total = in_sizes[0];              // B*1*H*W
    const int B = total / (H_DIM * W_DIM);

    dim3 grid(H_DIM / RPB, B);
    heightmap_loss_kernel<<<grid, NTHREADS>>>(gen, tgt, out,
                                              1.0 / (3.0 * (double)total));
}

// round 15
// speedup vs baseline: 1.2260x; 1.0118x over previous
#include <cuda_runtime.h>
#include <cuda_fp16.h>

#define H_DIM 512
#define W_DIM 512
#define RPB   16      // output rows per block -> 1024 blocks = single wave
#define NTHREADS 128  // 4 px/thread * 128 threads = 512 columns = full row
#define MAX_BLOCKS 8192

__device__ float    g_part[MAX_BLOCKS];
__device__ unsigned g_ticket;   // zero-init; restored to 0 by last block each run

// Raw per-row data: float4 + clamped halo scalars.
struct RawR { float4 v; float m, p; };

__device__ __forceinline__ RawR ldrow(const float* __restrict__ row,
                                      int x0, int xm, int xp) {
    RawR r;
    r.v = *reinterpret_cast<const float4*>(row + x0);
    r.m = __ldg(row + xm);
    r.p = __ldg(row + xp);
    return r;
}

// Per-row Sobel pieces in half2, pixel pairs (01) and (23):
//   d = val(x-1) - val(x+1) ; s = val(x-1) + 2 val(x) + val(x+1)
struct HS { __half2 d01, d23, s01, s23; };

__device__ __forceinline__ HS mk_hs(const RawR& a, __half2 two2) {
    // cvt.rn.f16x2.f32 packs two floats into one half2 in a single op
    __half2 mx = __floats2half2_rn(a.m,   a.v.x);
    __half2 xy = __floats2half2_rn(a.v.x, a.v.y);
    __half2 yz = __floats2half2_rn(a.v.y, a.v.z);
    __half2 zw = __floats2half2_rn(a.v.z, a.v.w);
    __half2 wp = __floats2half2_rn(a.v.w, a.p);
    HS r;
    r.d01 = __hsub2(mx, yz);                       // (m-y, x-z)
    r.d23 = __hsub2(yz, wp);                       // (y-w, z-p)
    r.s01 = __hadd2(__hfma2(two2, xy, mx), yz);    // (m+2x+y, x+2y+z)
    r.s23 = __hadd2(__hfma2(two2, zw, yz), wp);    // (y+2z+w, z+2w+p)
    return r;
}

// Packed normal for a pixel pair of one image, fully in half2:
//   q = gx^2+gy^2 ; length^2 = 0.0625 + 3.9375 q ; w = h2rsqrt(.) = 1/length
//   nx = gx*w, ny = gy*w, 4*nz = (1 - q/2)*w
__device__ __forceinline__ void nrm2(__half2 dP, __half2 dC, __half2 dN,
                                     __half2 sP, __half2 sN,
                                     __half2 two2, __half2 one2,
                                     __half2 c3, __half2 c0, __half2 cb,
                                     __half2& nx, __half2& ny, __half2& z4) {
    __half2 gx = __hadd2(__hfma2(two2, dC, dP), dN);
    __half2 gy = __hsub2(sP, sN);
    __half2 q  = __hfma2(gx, gx, __hmul2(gy, gy));
    __half2 w2 = h2rsqrt(__hfma2(c3, q, c0));
    __half2 su = __hfma2(cb, q, one2);             // 1 - q/2
    nx = __hmul2(gx, w2);
    ny = __hmul2(gy, w2);
    z4 = __hmul2(su, w2);      // 4*nz ; 0.25 folded into the final reduction
}

__global__ void __launch_bounds__(NTHREADS, 8)
heightmap_loss_kernel(const float* __restrict__ gen, const float* __restrict__ tgt,
                      float* __restrict__ out, double inv_n) {
    const int b    = blockIdx.y;
    const int y0   = blockIdx.x * RPB;
    const int lane = threadIdx.x & 31;
    const int x0   = threadIdx.x * 4;
    const int xm   = max(x0 - 1, 0);
    const int xp   = min(x0 + 4, W_DIM - 1);
    const int nblocks = gridDim.x * gridDim.y;
    const int bid     = blockIdx.y * gridDim.x + blockIdx.x;

    const __half2 two2 = __float2half2_rn(2.f);
    const __half2 one2 = __float2half2_rn(1.f);
    const __half2 c3   = __float2half2_rn(3.9375f);
    const __half2 c0   = __float2half2_rn(0.0625f);
    const __half2 cb   = __float2half2_rn(-0.5f);

    const float* __restrict__ gimg = gen + (size_t)b * (H_DIM * W_DIM);
    const float* __restrict__ timg = tgt + (size_t)b * (H_DIM * W_DIM);

    // rolling 3-row half2 window + 1-row raw prefetch buffer per image
    HS gP, gC, tP, tC;
    RawR gR, tR;     // raw data for the row that becomes N next iteration
    {
        int ym = max(y0 - 1, 0);
        gP = mk_hs(ldrow(gimg + ym * W_DIM, x0, xm, xp), two2);
        tP = mk_hs(ldrow(timg + ym * W_DIM, x0, xm, xp), two2);
        gC = mk_hs(ldrow(gimg + y0 * W_DIM, x0, xm, xp), two2);
        tC = mk_hs(ldrow(timg + y0 * W_DIM, x0, xm, xp), two2);
        gR = ldrow(gimg + (y0 + 1) * W_DIM, x0, xm, xp);   // y0+1 <= 497 < 512
        tR = ldrow(timg + (y0 + 1) * W_DIM, x0, xm, xp);
    }

    // independent packed accumulator pairs (A: px01, B: px23)
    __half2 axyA = __float2half2_rn(0.f), azA = axyA;
    __half2 axyB = axyA, azB = axyA;

    #pragma unroll
    for (int yy = 0; yy < RPB; yy++) {
        // Prefetch raw row yy+2 FIRST — consumers are a full iteration away.
        int yn2 = min(y0 + yy + 2, H_DIM - 1);
        RawR gR2 = ldrow(gimg + yn2 * W_DIM, x0, xm, xp);
        RawR tR2 = ldrow(timg + yn2 * W_DIM, x0, xm, xp);

        // N row from raw data loaded LAST iteration (already arrived).
        HS gN = mk_hs(gR, two2);
        HS tN = mk_hs(tR, two2);

        __half2 gnx, gny, gz4, tnx, tny, tz4;
        // pair 01
        nrm2(gP.d01, gC.d01, gN.d01, gP.s01, gN.s01,
             two2, one2, c3, c0, cb, gnx, gny, gz4);
        nrm2(tP.d01, tC.d01, tN.d01, tP.s01, tN.s01,
             two2, one2, c3, c0, cb, tnx, tny, tz4);
        axyA = __hadd2(axyA, __hadd2(__habs2(__hsub2(gnx, tnx)),
                                     __habs2(__hsub2(gny, tny))));
        azA  = __hadd2(azA, __habs2(__hsub2(gz4, tz4)));
        // pair 23
        nrm2(gP.d23, gC.d23, gN.d23, gP.s23, gN.s23,
             two2, one2, c3, c0, cb, gnx, gny, gz4);
        nrm2(tP.d23, tC.d23, tN.d23, tP.s23, tN.s23,
             two2, one2, c3, c0, cb, tnx, tny, tz4);
        axyB = __hadd2(axyB, __hadd2(__habs2(__hsub2(gnx, tnx)),
                                     __habs2(__hsub2(gny, tny))));
        azB  = __hadd2(azB, __habs2(__hsub2(gz4, tz4)));

        gP = gC; gC = gN; gR = gR2;
        tP = tC; tC = tN; tR = tR2;
    }

    // unpack to f32 and fold the 0.25 nz factor
    float axy = __low2float(axyA) + __high2float(axyA)
              + __low2float(axyB) + __high2float(axyB);
    float az  = __low2float(azA) + __high2float(azA)
              + __low2float(azB) + __high2float(azB);
    float acc = fmaf(0.25f, az, axy);

    // warp reduce
    #pragma unroll
    for (int o = 16; o > 0; o >>= 1)
        acc += __shfl_down_sync(0xffffffffu, acc, o);

    __shared__ float ws[NTHREADS / 32];
    __shared__ bool  isLast;
    if (lane == 0) ws[threadIdx.x >> 5] = acc;
    __syncthreads();
    if (threadIdx.x == 0) {
        g_part[bid] = ws[0] + ws[1] + ws[2] + ws[3];
        __threadfence();
        unsigned prev = atomicAdd(&g_ticket, 1u);
        isLast = (prev == (unsigned)(nblocks - 1));
    }
    __syncthreads();

    // Last block to finish performs the deterministic final reduction.
    if (isLast) {
        double s = 0.0;
        for (int i = threadIdx.x; i < nblocks; i += NTHREADS)
            s += (double)g_part[i];
        #pragma unroll
        for (int o = 16; o > 0; o >>= 1)
            s += __shfl_down_sync(0xffffffffu, s, o);
        __shared__ double ds[NTHREADS / 32];
        if (lane == 0) ds[threadIdx.x >> 5] = s;
        __syncthreads();
        if (threadIdx.x == 0) {
            double t = ds[0] + ds[1] + ds[2] + ds[3];
            out[0] = (float)(t * inv_n);
            g_ticket = 0u;   // restore invariant for graph replay
        }
    }
}

extern "C" void kernel_launch(void* const* d_in, const int* in_sizes, int n_in,
                              void* d_out, int out_size) {
    const float* gen = (const float*)d_in[0];
    const float* tgt = (const float*)d_in[1];
    float* out = (float*)d_out;

    const int total = in_sizes[0];              // B*1*H*W
    const int B = total / (H_DIM * W_DIM);

    dim3 grid(H_DIM / RPB, B);
    heightmap_loss_kernel<<<grid, NTHREADS>>>(gen, tgt, out,
                                              1.0 / (3.0 * (double)total));
}